// round 1
// baseline (speedup 1.0000x reference)
#include <cuda_runtime.h>
#include <math.h>

#define NRES 768
#define BATCH 2
#define KTOP 30
#define DP 128
#define INFV 1e10f

typedef unsigned long long ull;

// ---------- f32x2 packed FMA helpers (Blackwell FFMA2) ----------
__device__ __forceinline__ ull fma2(ull a, ull b, ull c){
    ull d; asm("fma.rn.f32x2 %0, %1, %2, %3;" : "=l"(d) : "l"(a), "l"(b), "l"(c)); return d;
}
__device__ __forceinline__ ull packdup(float x){
    ull r; asm("mov.b64 %0, {%1, %2};" : "=l"(r) : "f"(x), "f"(x)); return r;
}
__device__ __forceinline__ void unpack2(ull v, float& lo, float& hi){
    asm("mov.b64 {%0, %1}, %2;" : "=f"(lo), "=f"(hi) : "l"(v));
}
__device__ __forceinline__ float gelu_t(float x){
    // jax.nn.gelu approximate=True (tanh)
    float x3 = x*x*x;
    return 0.5f*x*(1.0f + tanhf(0.7978845608028654f*(x + 0.044715f*x3)));
}
// order-preserving float->uint key (ascending)
__device__ __forceinline__ unsigned okey(float v){
    unsigned u = __float_as_uint(v);
    return (u & 0x80000000u) ? ~u : (u | 0x80000000u);
}
__device__ __forceinline__ ull umin64(ull a, ull b){ return a < b ? a : b; }

struct Smem {
    float w2[DP*DP];      // 64 KB: current W2 (Wa2 or Wd2)
    ull   h2[16*DP];      // 16 KB: h packed as (h[2p], h[2p+1]) per d; pair 15 zeroed
    float d4[NRES];
    float dists[NRES];
    float w1a[5*DP];
    float w1d[3*DP];
    float b1a[DP], b1d[DP], b2a[DP], b2d[DP];
    float feats[32][6];   // [eye, conn, da0, da1, da2, dist]
    ull   red[8];
    int   sidx[32];
    float tiRi[12];       // t_i(3), R row-major 3x3 (9)
};

// ============ kernel 1: s = W_tf + b_tf broadcast ============
__global__ void s_kernel(const float* __restrict__ W_tf, const float* __restrict__ b_tf,
                         float* __restrict__ out){
    __shared__ float v[256];
    if (threadIdx.x < 256) v[threadIdx.x] = W_tf[threadIdx.x] + b_tf[threadIdx.x];
    __syncthreads();
    int e = blockIdx.x * blockDim.x + threadIdx.x;
    out[e] = v[e & 255];
}

// ============ kernel 2: topk + features + both embeds, one block per (b,i) ============
__global__ __launch_bounds__(256) void embed_kernel(
    const int* __restrict__ ri, const float* __restrict__ frames, const float* __restrict__ smask,
    const float* __restrict__ Wa1, const float* __restrict__ ba1,
    const float* __restrict__ Wa2, const float* __restrict__ ba2,
    const float* __restrict__ Wd1, const float* __restrict__ bd1,
    const float* __restrict__ Wd2, const float* __restrict__ bd2,
    float* __restrict__ out_ang, float* __restrict__ out_dst)
{
    extern __shared__ unsigned char smraw[];
    Smem& S = *reinterpret_cast<Smem*>(smraw);
    const int tid = threadIdx.x;
    const int bi = blockIdx.x;
    const int b  = bi / NRES;
    const int i  = bi - b*NRES;

    // small weights -> smem
    for (int e = tid; e < 5*DP; e += 256) S.w1a[e] = Wa1[e];
    for (int e = tid; e < 3*DP; e += 256) S.w1d[e] = Wd1[e];
    if (tid < DP){ S.b1a[tid]=ba1[tid]; S.b1d[tid]=bd1[tid]; S.b2a[tid]=ba2[tid]; S.b2d[tid]=bd2[tid]; }
    if (tid < 3) S.tiRi[tid] = frames[(size_t)(b*NRES+i)*16 + tid*4 + 3];
    if (tid >= 32 && tid < 41){
        int e = tid - 32;
        S.tiRi[3+e] = frames[(size_t)(b*NRES+i)*16 + (e/3)*4 + (e%3)];
    }
    __syncthreads();

    const float ti0 = S.tiRi[0], ti1 = S.tiRi[1], ti2 = S.tiRi[2];
    const int   rii = ri[b*NRES + i];
    const float mi  = smask[b*NRES + i];

    // distances + masked selection keys (3 elems/thread, 768 = 256*3)
    #pragma unroll
    for (int e = 0; e < 3; e++){
        int j = tid*3 + e;
        const float* fj = frames + (size_t)(b*NRES + j)*16;
        float dx = fj[3]-ti0, dy = fj[7]-ti1, dz = fj[11]-ti2;
        float d = sqrtf(dx*dx + dy*dy + dz*dz);
        S.dists[j] = d;
        bool conn = abs(rii - ri[b*NRES + j]) == 1;
        bool m = (mi != 0.f) && (smask[b*NRES + j] != 0.f);
        float v = conn ? -INFV : (!m ? INFV : ((j == i) ? INFV : d));
        S.d4[j] = v;
    }
    __syncthreads();

    // top-30 smallest by (value, index) - matches lax.top_k order exactly
    for (int it = 0; it < KTOP; it++){
        ull best = ~0ull;
        #pragma unroll
        for (int e = 0; e < 3; e++){
            int j = tid*3 + e;
            ull k = ((ull)okey(S.d4[j]) << 32) | (unsigned)j;
            best = umin64(best, k);
        }
        #pragma unroll
        for (int off = 16; off; off >>= 1)
            best = umin64(best, __shfl_down_sync(0xffffffffu, best, off));
        if ((tid & 31) == 0) S.red[tid >> 5] = best;
        __syncthreads();
        if (tid < 32){
            ull v = (tid < 8) ? S.red[tid] : ~0ull;
            #pragma unroll
            for (int off = 4; off; off >>= 1)
                v = umin64(v, __shfl_down_sync(0xffffffffu, v, off));
            if (tid == 0){
                int sel = (int)(v & 0xffffffffu);
                S.sidx[it] = sel;
                S.d4[sel] = 3.0e38f;
            }
        }
        __syncthreads();
    }

    // per-k features
    if (tid < KTOP){
        int sel = S.sidx[tid];
        const float* fj = frames + (size_t)(b*NRES + sel)*16;
        float dx = fj[3]-ti0, dy = fj[7]-ti1, dz = fj[11]-ti2;
        float d = S.dists[sel];
        float inv = (d > 0.f) ? (1.0f/d) : 0.f;
        // t_rel[y] = sum_x R[x][y] * diff[x]
        float tr0 = S.tiRi[3+0]*dx + S.tiRi[3+3]*dy + S.tiRi[3+6]*dz;
        float tr1 = S.tiRi[3+1]*dx + S.tiRi[3+4]*dy + S.tiRi[3+7]*dz;
        float tr2 = S.tiRi[3+2]*dx + S.tiRi[3+5]*dy + S.tiRi[3+8]*dz;
        S.feats[tid][0] = (sel == i) ? 1.f : 0.f;
        S.feats[tid][1] = (abs(rii - ri[b*NRES + sel]) == 1) ? 1.f : 0.f;
        S.feats[tid][2] = tr0*inv;
        S.feats[tid][3] = tr1*inv;
        S.feats[tid][4] = tr2*inv;
        S.feats[tid][5] = d;
    }

    const int pg = tid >> 5;   // warp id = pair-group (2 k-pairs)
    const int ct = tid & 31;   // column tile (4 cols)

    for (int emb = 0; emb < 2; emb++){
        __syncthreads();  // previous gemm done reading h2/w2 (and feats ready)
        // h = gelu(x @ W1 + b1), packed two k-rows per f32x2 slot
        for (int e = tid; e < 4096; e += 256){
            int k = e >> 7, c = e & 127;
            float h = 0.f;
            if (k < KTOP){
                const float* f = S.feats[k];
                float pre;
                if (emb == 0)
                    pre = S.b1a[c] + f[0]*S.w1a[c] + f[1]*S.w1a[DP+c]
                        + f[2]*S.w1a[2*DP+c] + f[3]*S.w1a[3*DP+c] + f[4]*S.w1a[4*DP+c];
                else
                    pre = S.b1d[c] + f[0]*S.w1d[c] + f[1]*S.w1d[DP+c] + f[5]*S.w1d[2*DP+c];
                h = gelu_t(pre);
            }
            ((float*)S.h2)[((k>>1)*DP + c)*2 + (k & 1)] = h;
        }
        // W2 -> smem
        const float4* W2g = (const float4*)(emb ? Wd2 : Wa2);
        for (int e = tid; e < 4096; e += 256) ((float4*)S.w2)[e] = W2g[e];
        __syncthreads();

        // (30x128) @ (128x128) with FFMA2: warp owns pairs {2pg, 2pg+1}, lane owns 4 cols
        const ull* hp0 = S.h2 + (2*pg)*DP;
        const ull* hp1 = S.h2 + (2*pg+1)*DP;
        ull a00=0,a01=0,a02=0,a03=0, a10=0,a11=0,a12=0,a13=0;
        #pragma unroll 4
        for (int d = 0; d < DP; d++){
            ull hv0 = hp0[d];
            ull hv1 = hp1[d];
            float4 w = ((const float4*)S.w2)[d*32 + ct];
            ull bx = packdup(w.x), by = packdup(w.y), bz = packdup(w.z), bw = packdup(w.w);
            a00 = fma2(hv0, bx, a00); a01 = fma2(hv0, by, a01);
            a02 = fma2(hv0, bz, a02); a03 = fma2(hv0, bw, a03);
            a10 = fma2(hv1, bx, a10); a11 = fma2(hv1, by, a11);
            a12 = fma2(hv1, bz, a12); a13 = fma2(hv1, bw, a13);
        }
        float4 bv = ((const float4*)(emb ? S.b2d : S.b2a))[ct];
        float* og = emb ? out_dst : out_ang;
        size_t base4 = (size_t)bi * KTOP * 32;
        {   // pair 2pg -> rows k0 = 4pg, 4pg+1 (always < 30)
            int k0 = 4*pg;
            float l0,u0,l1,u1,l2,u2,l3,u3;
            unpack2(a00,l0,u0); unpack2(a01,l1,u1); unpack2(a02,l2,u2); unpack2(a03,l3,u3);
            float4 r0 = make_float4(l0+bv.x, l1+bv.y, l2+bv.z, l3+bv.w);
            float4 r1 = make_float4(u0+bv.x, u1+bv.y, u2+bv.z, u3+bv.w);
            ((float4*)og)[base4 + (size_t)k0*32 + ct]     = r0;
            ((float4*)og)[base4 + (size_t)(k0+1)*32 + ct] = r1;
        }
        {   // pair 2pg+1 -> rows 4pg+2, 4pg+3 (pg=7 rows 30,31 are dummies)
            int k0 = 4*pg + 2;
            float l0,u0,l1,u1,l2,u2,l3,u3;
            unpack2(a10,l0,u0); unpack2(a11,l1,u1); unpack2(a12,l2,u2); unpack2(a13,l3,u3);
            if (k0 < KTOP){
                float4 r0 = make_float4(l0+bv.x, l1+bv.y, l2+bv.z, l3+bv.w);
                ((float4*)og)[base4 + (size_t)k0*32 + ct] = r0;
            }
            if (k0 + 1 < KTOP){
                float4 r1 = make_float4(u0+bv.x, u1+bv.y, u2+bv.z, u3+bv.w);
                ((float4*)og)[base4 + (size_t)(k0+1)*32 + ct] = r1;
            }
        }
    }
}

// ============ kernel 3: relpos table broadcast (HBM-write bound) ============
__global__ __launch_bounds__(256) void relpos_kernel(
    const int* __restrict__ ri, const float* __restrict__ W_rp, const float* __restrict__ b_rp,
    float* __restrict__ out)
{
    __shared__ float T[65*DP];
    for (int e = threadIdx.x; e < 65*DP; e += 256) T[e] = W_rp[e] + b_rp[e & 127];
    __syncthreads();
    const int lane = threadIdx.x & 31;
    const int w    = threadIdx.x >> 5;
    const int total = BATCH*NRES*NRES;
    for (int r = blockIdx.x*8 + w; r < total; r += gridDim.x*8){
        int bb  = r / (NRES*NRES);
        int rem = r - bb*(NRES*NRES);
        int ii  = rem / NRES;
        int jj  = rem - ii*NRES;
        int d = ri[bb*NRES + ii] - ri[bb*NRES + jj];
        d = min(32, max(-32, d)) + 32;
        float4 v = ((const float4*)T)[d*32 + lane];
        ((float4*)out)[(size_t)r*32 + lane] = v;
    }
}

extern "C" void kernel_launch(void* const* d_in, const int* in_sizes, int n_in,
                              void* d_out, int out_size)
{
    const int*   ri     = (const int*)  d_in[1];
    const float* frames = (const float*)d_in[2];
    const float* smaskp = (const float*)d_in[3];
    const float* W_tf   = (const float*)d_in[4];
    const float* b_tf   = (const float*)d_in[5];
    const float* Wa1    = (const float*)d_in[6];
    const float* ba1    = (const float*)d_in[7];
    const float* Wa2    = (const float*)d_in[8];
    const float* ba2    = (const float*)d_in[9];
    const float* Wd1    = (const float*)d_in[10];
    const float* bd1    = (const float*)d_in[11];
    const float* Wd2    = (const float*)d_in[12];
    const float* bd2    = (const float*)d_in[13];
    const float* W_rp   = (const float*)d_in[14];
    const float* b_rp   = (const float*)d_in[15];

    float* out     = (float*)d_out;
    float* out_s   = out;                                       // (2,768,256)
    float* out_ang = out_s   + (size_t)BATCH*NRES*256;          // (2,768,30,128)
    float* out_dst = out_ang + (size_t)BATCH*NRES*KTOP*DP;      // (2,768,30,128)
    float* out_rp  = out_dst + (size_t)BATCH*NRES*KTOP*DP;      // (2,768,768,128)

    cudaFuncSetAttribute(embed_kernel, cudaFuncAttributeMaxDynamicSharedMemorySize,
                         (int)sizeof(Smem));

    s_kernel<<<768, 512>>>(W_tf, b_tf, out_s);
    embed_kernel<<<BATCH*NRES, 256, sizeof(Smem)>>>(
        ri, frames, smaskp, Wa1, ba1, Wa2, ba2, Wd1, bd1, Wd2, bd2, out_ang, out_dst);
    relpos_kernel<<<1184, 256>>>(ri, W_rp, b_rp, out_rp);
}

// round 2
// speedup vs baseline: 1.2297x; 1.2297x over previous
#include <cuda_runtime.h>
#include <math.h>

#define NRES 768
#define BATCH 2
#define KTOP 30
#define DP 128
#define INFV 1e10f
#define NE   (BATCH*NRES)          // 1536 embed sites (even blocks)
#define NRB  1536                  // relpos blocks (odd blocks)
#define TOTROWS (BATCH*NRES*NRES)  // 1,179,648 pair rows

typedef unsigned long long ull;

// ---------- f32x2 packed FMA helpers (Blackwell FFMA2) ----------
__device__ __forceinline__ ull fma2(ull a, ull b, ull c){
    ull d; asm("fma.rn.f32x2 %0, %1, %2, %3;" : "=l"(d) : "l"(a), "l"(b), "l"(c)); return d;
}
__device__ __forceinline__ ull packdup(float x){
    ull r; asm("mov.b64 %0, {%1, %2};" : "=l"(r) : "f"(x), "f"(x)); return r;
}
__device__ __forceinline__ void unpack2(ull v, float& lo, float& hi){
    asm("mov.b64 {%0, %1}, %2;" : "=f"(lo), "=f"(hi) : "l"(v));
}
__device__ __forceinline__ float gelu_t(float x){
    float x3 = x*x*x;
    return 0.5f*x*(1.0f + tanhf(0.7978845608028654f*(x + 0.044715f*x3)));
}
// order-preserving float->uint key (ascending)
__device__ __forceinline__ unsigned okey(float v){
    unsigned u = __float_as_uint(v);
    return (u & 0x80000000u) ? ~u : (u | 0x80000000u);
}
__device__ __forceinline__ ull umin64(ull a, ull b){ return a < b ? a : b; }

struct SmemE {
    float w2[DP*DP];      // 64 KB: current W2
    ull   h2[16*DP];      // 16 KB: h packed (h[2p], h[2p+1])
    ull   keys[NRES];     // 6 KB: (okey(d4)<<32)|j
    float dists[NRES];
    float w1a[5*DP];
    float w1d[3*DP];
    float b1a[DP], b1d[DP], b2a[DP], b2d[DP];
    float feats[32][6];   // [eye, conn, da0, da1, da2, dist]
    int   sidx[32];
    float tiRi[12];
};
struct SmemR {
    float T[65*DP];       // 33 KB relpos table
    float sv[256];        // s row values
};

__device__ __forceinline__ void embed_role(
    unsigned char* smraw, int site,
    const int* __restrict__ ri, const float* __restrict__ frames, const float* __restrict__ smask,
    const float* __restrict__ Wa1, const float* __restrict__ ba1,
    const float* __restrict__ Wa2, const float* __restrict__ ba2,
    const float* __restrict__ Wd1, const float* __restrict__ bd1,
    const float* __restrict__ Wd2, const float* __restrict__ bd2,
    float* __restrict__ out_ang, float* __restrict__ out_dst)
{
    SmemE& S = *reinterpret_cast<SmemE*>(smraw);
    const int tid = threadIdx.x;
    const int b  = site / NRES;
    const int i  = site - b*NRES;

    // small weights -> smem
    for (int e = tid; e < 5*DP; e += 256) S.w1a[e] = Wa1[e];
    for (int e = tid; e < 3*DP; e += 256) S.w1d[e] = Wd1[e];
    if (tid < DP){ S.b1a[tid]=ba1[tid]; S.b1d[tid]=bd1[tid]; S.b2a[tid]=ba2[tid]; S.b2d[tid]=bd2[tid]; }
    if (tid < 3) S.tiRi[tid] = frames[(size_t)(b*NRES+i)*16 + tid*4 + 3];
    if (tid >= 32 && tid < 41){
        int e = tid - 32;
        S.tiRi[3+e] = frames[(size_t)(b*NRES+i)*16 + (e/3)*4 + (e%3)];
    }
    __syncthreads();

    const float ti0 = S.tiRi[0], ti1 = S.tiRi[1], ti2 = S.tiRi[2];
    const int   rii = ri[b*NRES + i];
    const float mi  = smask[b*NRES + i];

    // distances + masked selection keys
    #pragma unroll
    for (int e = 0; e < 3; e++){
        int j = tid*3 + e;
        const float* fj = frames + (size_t)(b*NRES + j)*16;
        float dx = fj[3]-ti0, dy = fj[7]-ti1, dz = fj[11]-ti2;
        float d = sqrtf(dx*dx + dy*dy + dz*dz);
        S.dists[j] = d;
        bool conn = abs(rii - ri[b*NRES + j]) == 1;
        bool m = (mi != 0.f) && (smask[b*NRES + j] != 0.f);
        float v = conn ? -INFV : (!m ? INFV : ((j == i) ? INFV : d));
        S.keys[j] = ((ull)okey(v) << 32) | (unsigned)j;
    }
    __syncthreads();

    // warp0: top-30 (shfl-only, no block barriers); warps 1-7: prefetch Wa2
    if (tid >= 32){
        for (int e = tid - 32; e < 4096; e += 224)
            ((float4*)S.w2)[e] = ((const float4*)Wa2)[e];
    } else {
        const int lane = tid;
        for (int it = 0; it < KTOP; it++){
            ull m = ~0ull;
            #pragma unroll
            for (int e = 0; e < 24; e++) m = umin64(m, S.keys[e*32 + lane]);
            #pragma unroll
            for (int off = 16; off; off >>= 1)
                m = umin64(m, __shfl_xor_sync(0xffffffffu, m, off));
            int j = (int)(m & 0xffffffffu);
            if (lane == 0){ S.sidx[it] = j; S.keys[j] = ~0ull; }
            __syncwarp();
        }
        // per-k features (still warp 0)
        if (lane < KTOP){
            int sel = S.sidx[lane];
            const float* fj = frames + (size_t)(b*NRES + sel)*16;
            float dx = fj[3]-ti0, dy = fj[7]-ti1, dz = fj[11]-ti2;
            float d = S.dists[sel];
            float inv = (d > 0.f) ? (1.0f/d) : 0.f;
            float tr0 = S.tiRi[3+0]*dx + S.tiRi[3+3]*dy + S.tiRi[3+6]*dz;
            float tr1 = S.tiRi[3+1]*dx + S.tiRi[3+4]*dy + S.tiRi[3+7]*dz;
            float tr2 = S.tiRi[3+2]*dx + S.tiRi[3+5]*dy + S.tiRi[3+8]*dz;
            S.feats[lane][0] = (sel == i) ? 1.f : 0.f;
            S.feats[lane][1] = (abs(rii - ri[b*NRES + sel]) == 1) ? 1.f : 0.f;
            S.feats[lane][2] = tr0*inv;
            S.feats[lane][3] = tr1*inv;
            S.feats[lane][4] = tr2*inv;
            S.feats[lane][5] = d;
        }
    }
    __syncthreads();

    const int pg = tid >> 5;   // warp id = pair-group (2 k-pairs)
    const int ct = tid & 31;   // column tile (4 cols)
    const size_t base4 = (size_t)site * KTOP * 32;

    #pragma unroll
    for (int emb = 0; emb < 2; emb++){
        // h = gelu(x @ W1 + b1), packed two k-rows per f32x2 slot
        for (int e = tid; e < 4096; e += 256){
            int k = e >> 7, c = e & 127;
            float h = 0.f;
            if (k < KTOP){
                const float* f = S.feats[k];
                float pre;
                if (emb == 0)
                    pre = S.b1a[c] + f[0]*S.w1a[c] + f[1]*S.w1a[DP+c]
                        + f[2]*S.w1a[2*DP+c] + f[3]*S.w1a[3*DP+c] + f[4]*S.w1a[4*DP+c];
                else
                    pre = S.b1d[c] + f[0]*S.w1d[c] + f[1]*S.w1d[DP+c] + f[5]*S.w1d[2*DP+c];
                h = gelu_t(pre);
            }
            ((float*)S.h2)[((k>>1)*DP + c)*2 + (k & 1)] = h;
        }
        __syncthreads();  // h2 (and w2 for emb0 / reloaded w2 for emb1) ready

        // (30x128) @ (128x128) with FFMA2
        const ull* hp0 = S.h2 + (2*pg)*DP;
        const ull* hp1 = S.h2 + (2*pg+1)*DP;
        ull a00=0,a01=0,a02=0,a03=0, a10=0,a11=0,a12=0,a13=0;
        #pragma unroll 4
        for (int d = 0; d < DP; d++){
            ull hv0 = hp0[d];
            ull hv1 = hp1[d];
            float4 w = ((const float4*)S.w2)[d*32 + ct];
            ull bx = packdup(w.x), by = packdup(w.y), bz = packdup(w.z), bw = packdup(w.w);
            a00 = fma2(hv0, bx, a00); a01 = fma2(hv0, by, a01);
            a02 = fma2(hv0, bz, a02); a03 = fma2(hv0, bw, a03);
            a10 = fma2(hv1, bx, a10); a11 = fma2(hv1, by, a11);
            a12 = fma2(hv1, bz, a12); a13 = fma2(hv1, bw, a13);
        }
        float4 bv = ((const float4*)(emb ? S.b2d : S.b2a))[ct];
        float* og = emb ? out_dst : out_ang;
        {   // pair 2pg -> rows 4pg, 4pg+1 (always < 30)
            int k0 = 4*pg;
            float l0,u0,l1,u1,l2,u2,l3,u3;
            unpack2(a00,l0,u0); unpack2(a01,l1,u1); unpack2(a02,l2,u2); unpack2(a03,l3,u3);
            ((float4*)og)[base4 + (size_t)k0*32 + ct]     = make_float4(l0+bv.x, l1+bv.y, l2+bv.z, l3+bv.w);
            ((float4*)og)[base4 + (size_t)(k0+1)*32 + ct] = make_float4(u0+bv.x, u1+bv.y, u2+bv.z, u3+bv.w);
        }
        {   // pair 2pg+1 -> rows 4pg+2, 4pg+3 (pg=7 rows 30,31 dropped)
            int k0 = 4*pg + 2;
            float l0,u0,l1,u1,l2,u2,l3,u3;
            unpack2(a10,l0,u0); unpack2(a11,l1,u1); unpack2(a12,l2,u2); unpack2(a13,l3,u3);
            if (k0 < KTOP)
                ((float4*)og)[base4 + (size_t)k0*32 + ct] = make_float4(l0+bv.x, l1+bv.y, l2+bv.z, l3+bv.w);
            if (k0 + 1 < KTOP)
                ((float4*)og)[base4 + (size_t)(k0+1)*32 + ct] = make_float4(u0+bv.x, u1+bv.y, u2+bv.z, u3+bv.w);
        }
        if (emb == 0){
            __syncthreads();   // GEMM0 done reading w2/h2
            for (int e = tid; e < 4096; e += 256)
                ((float4*)S.w2)[e] = ((const float4*)Wd2)[e];
            // h2 refill happens at top of emb=1 iteration, then barrier
        }
    }
}

__device__ __forceinline__ void relpos_role(
    unsigned char* smraw, int rblk,
    const int* __restrict__ ri,
    const float* __restrict__ W_rp, const float* __restrict__ b_rp,
    const float* __restrict__ W_tf, const float* __restrict__ b_tf,
    float* __restrict__ out_s, float* __restrict__ out_rp)
{
    SmemR& S = *reinterpret_cast<SmemR*>(smraw);
    const int tid = threadIdx.x;
    for (int e = tid; e < 65*DP; e += 256) S.T[e] = W_rp[e] + b_rp[e & 127];
    S.sv[tid] = W_tf[tid] + b_tf[tid];
    __syncthreads();

    // s slice: 64 float4 per block (1536 blocks * 64 = 98304 = full s)
    if (tid < 64){
        int i4 = rblk*64 + tid;
        ((float4*)out_s)[i4] = ((const float4*)S.sv)[i4 & 63];
    }

    const int lane = tid & 31;
    const int w    = tid >> 5;
    for (int r = rblk*8 + w; r < TOTROWS; r += NRB*8){
        int bb  = r / (NRES*NRES);
        int rem = r - bb*(NRES*NRES);
        int ii  = rem / NRES;
        int jj  = rem - ii*NRES;
        int d = ri[bb*NRES + ii] - ri[bb*NRES + jj];
        d = min(32, max(-32, d)) + 32;
        float4 v = ((const float4*)S.T)[d*32 + lane];
        ((float4*)out_rp)[(size_t)r*32 + lane] = v;
    }
}

__global__ __launch_bounds__(256, 2) void fused_kernel(
    const int* __restrict__ ri, const float* __restrict__ frames, const float* __restrict__ smask,
    const float* __restrict__ W_tf, const float* __restrict__ b_tf,
    const float* __restrict__ Wa1, const float* __restrict__ ba1,
    const float* __restrict__ Wa2, const float* __restrict__ ba2,
    const float* __restrict__ Wd1, const float* __restrict__ bd1,
    const float* __restrict__ Wd2, const float* __restrict__ bd2,
    const float* __restrict__ W_rp, const float* __restrict__ b_rp,
    float* __restrict__ out_s, float* __restrict__ out_ang,
    float* __restrict__ out_dst, float* __restrict__ out_rp)
{
    extern __shared__ unsigned char smraw[];
    const int bx = blockIdx.x;
    if ((bx & 1) == 0){
        embed_role(smraw, bx >> 1, ri, frames, smask,
                   Wa1, ba1, Wa2, ba2, Wd1, bd1, Wd2, bd2, out_ang, out_dst);
    } else {
        relpos_role(smraw, bx >> 1, ri, W_rp, b_rp, W_tf, b_tf, out_s, out_rp);
    }
}

extern "C" void kernel_launch(void* const* d_in, const int* in_sizes, int n_in,
                              void* d_out, int out_size)
{
    const int*   ri     = (const int*)  d_in[1];
    const float* frames = (const float*)d_in[2];
    const float* smaskp = (const float*)d_in[3];
    const float* W_tf   = (const float*)d_in[4];
    const float* b_tf   = (const float*)d_in[5];
    const float* Wa1    = (const float*)d_in[6];
    const float* ba1    = (const float*)d_in[7];
    const float* Wa2    = (const float*)d_in[8];
    const float* ba2    = (const float*)d_in[9];
    const float* Wd1    = (const float*)d_in[10];
    const float* bd1    = (const float*)d_in[11];
    const float* Wd2    = (const float*)d_in[12];
    const float* bd2    = (const float*)d_in[13];
    const float* W_rp   = (const float*)d_in[14];
    const float* b_rp   = (const float*)d_in[15];

    float* out     = (float*)d_out;
    float* out_s   = out;                                       // (2,768,256)
    float* out_ang = out_s   + (size_t)BATCH*NRES*256;          // (2,768,30,128)
    float* out_dst = out_ang + (size_t)BATCH*NRES*KTOP*DP;      // (2,768,30,128)
    float* out_rp  = out_dst + (size_t)BATCH*NRES*KTOP*DP;      // (2,768,768,128)

    int smem = (int)(sizeof(SmemE) > sizeof(SmemR) ? sizeof(SmemE) : sizeof(SmemR));
    cudaFuncSetAttribute(fused_kernel, cudaFuncAttributeMaxDynamicSharedMemorySize, smem);

    fused_kernel<<<NE + NRB, 256, smem>>>(
        ri, frames, smaskp, W_tf, b_tf,
        Wa1, ba1, Wa2, ba2, Wd1, bd1, Wd2, bd2, W_rp, b_rp,
        out_s, out_ang, out_dst, out_rp);
}

// round 3
// speedup vs baseline: 1.3541x; 1.1012x over previous
#include <cuda_runtime.h>
#include <math.h>

#define NRES 768
#define BATCH 2
#define KTOP 30
#define DP 128
#define INFV 1e10f
#define NE   (BATCH*NRES)          // 1536 embed sites (even blocks)
#define NRB  1536                  // relpos blocks (odd blocks)
#define TOTROWS (BATCH*NRES*NRES)  // 1,179,648 pair rows

typedef unsigned long long ull;

__device__ __forceinline__ ull fma2(ull a, ull b, ull c){
    ull d; asm("fma.rn.f32x2 %0, %1, %2, %3;" : "=l"(d) : "l"(a), "l"(b), "l"(c)); return d;
}
__device__ __forceinline__ ull packdup(float x){
    ull r; asm("mov.b64 %0, {%1, %2};" : "=l"(r) : "f"(x), "f"(x)); return r;
}
__device__ __forceinline__ void unpack2(ull v, float& lo, float& hi){
    asm("mov.b64 {%0, %1}, %2;" : "=f"(lo), "=f"(hi) : "l"(v));
}
__device__ __forceinline__ float gelu_t(float x){
    float x3 = x*x*x;
    return 0.5f*x*(1.0f + tanhf(0.7978845608028654f*(x + 0.044715f*x3)));
}
__device__ __forceinline__ unsigned okey(float v){
    unsigned u = __float_as_uint(v);
    return (u & 0x80000000u) ? ~u : (u | 0x80000000u);
}
__device__ __forceinline__ ull umin64(ull a, ull b){ return a < b ? a : b; }

struct SmemE {
    ull   h2[DP*16];      // 16 KB: h2[d][pair] = (h[2p], h[2p+1]) packed f32x2
    ull   keys[NRES];     // 6 KB
    float dists[NRES];    // 3 KB
    float w1a[5*DP];
    float w1d[3*DP];
    float b1a[DP], b1d[DP], b2a[DP], b2d[DP];
    float fe[6][32];      // SoA feats: eye, conn, da0, da1, da2, dist
    float tiRi[12];
};
struct SmemR {
    float T[65*DP];       // 33.3 KB relpos table
    float sv[256];
};

__device__ __forceinline__ void embed_role(
    unsigned char* smraw, int site,
    const int* __restrict__ ri, const float* __restrict__ frames, const float* __restrict__ smask,
    const float* __restrict__ Wa1, const float* __restrict__ ba1,
    const float* __restrict__ Wa2, const float* __restrict__ ba2,
    const float* __restrict__ Wd1, const float* __restrict__ bd1,
    const float* __restrict__ Wd2, const float* __restrict__ bd2,
    float* __restrict__ out_ang, float* __restrict__ out_dst)
{
    SmemE& S = *reinterpret_cast<SmemE*>(smraw);
    const int tid = threadIdx.x;
    const int b  = site / NRES;
    const int i  = site - b*NRES;

    for (int e = tid; e < 5*DP; e += 256) S.w1a[e] = Wa1[e];
    for (int e = tid; e < 3*DP; e += 256) S.w1d[e] = Wd1[e];
    if (tid < DP){ S.b1a[tid]=ba1[tid]; S.b1d[tid]=bd1[tid]; S.b2a[tid]=ba2[tid]; S.b2d[tid]=bd2[tid]; }
    if (tid < 3) S.tiRi[tid] = frames[(size_t)(b*NRES+i)*16 + tid*4 + 3];
    if (tid >= 32 && tid < 41){
        int e = tid - 32;
        S.tiRi[3+e] = frames[(size_t)(b*NRES+i)*16 + (e/3)*4 + (e%3)];
    }
    __syncthreads();

    const float ti0 = S.tiRi[0], ti1 = S.tiRi[1], ti2 = S.tiRi[2];
    const int   rii = ri[b*NRES + i];
    const float mi  = smask[b*NRES + i];

    // distances + selection keys: key j lives at S.keys[j], owner lane = j&31
    #pragma unroll
    for (int e = 0; e < 3; e++){
        int j = tid*3 + e;
        const float* fj = frames + (size_t)(b*NRES + j)*16;
        float dx = fj[3]-ti0, dy = fj[7]-ti1, dz = fj[11]-ti2;
        float d = sqrtf(dx*dx + dy*dy + dz*dz);
        S.dists[j] = d;
        bool conn = abs(rii - ri[b*NRES + j]) == 1;
        bool m = (mi != 0.f) && (smask[b*NRES + j] != 0.f);
        float v = conn ? -INFV : (!m ? INFV : ((j == i) ? INFV : d));
        S.keys[j] = ((ull)okey(v) << 32) | (unsigned)j;
    }
    __syncthreads();

    // warp0: top-30 via per-lane cached min + winner-only rescan; sel kept in regs
    if (tid < 32){
        const int lane = tid;
        ull mymin = ~0ull;
        #pragma unroll
        for (int e = 0; e < 24; e++) mymin = umin64(mymin, S.keys[e*32 + lane]);
        int mysel = -1;
        for (int it = 0; it < KTOP; it++){
            ull m = mymin;
            #pragma unroll
            for (int off = 16; off; off >>= 1)
                m = umin64(m, __shfl_xor_sync(0xffffffffu, m, off));
            if (it == lane) mysel = (int)(m & 0xffffffffu);
            if (m == mymin){               // unique winner (index embedded in key)
                S.keys[(int)(m & 0xffffffffu)] = ~0ull;   // my own slot
                ull t = ~0ull;
                #pragma unroll
                for (int e = 0; e < 24; e++) t = umin64(t, S.keys[e*32 + lane]);
                mymin = t;
            }
        }
        __syncwarp();
        if (lane < KTOP){
            int sel = mysel;
            const float* fj = frames + (size_t)(b*NRES + sel)*16;
            float dx = fj[3]-ti0, dy = fj[7]-ti1, dz = fj[11]-ti2;
            float d = S.dists[sel];
            float inv = (d > 0.f) ? (1.0f/d) : 0.f;
            float tr0 = S.tiRi[3+0]*dx + S.tiRi[3+3]*dy + S.tiRi[3+6]*dz;
            float tr1 = S.tiRi[3+1]*dx + S.tiRi[3+4]*dy + S.tiRi[3+7]*dz;
            float tr2 = S.tiRi[3+2]*dx + S.tiRi[3+5]*dy + S.tiRi[3+8]*dz;
            S.fe[0][lane] = (sel == i) ? 1.f : 0.f;
            S.fe[1][lane] = (abs(rii - ri[b*NRES + sel]) == 1) ? 1.f : 0.f;
            S.fe[2][lane] = tr0*inv;
            S.fe[3][lane] = tr1*inv;
            S.fe[4][lane] = tr2*inv;
            S.fe[5][lane] = d;
        }
        if (lane >= KTOP){   // zero feats of dummy rows 30,31 (h=0 path anyway)
            #pragma unroll
            for (int f = 0; f < 6; f++) S.fe[f][lane] = 0.f;
        }
    }
    __syncthreads();

    const int lane  = tid & 31;
    const int wq    = (tid >> 5) & 3;    // col quarter
    const int g     = tid >> 7;          // pair group 0/1
    const int c     = wq*32 + lane;
    const int pbase = g*8;
    const size_t base = (size_t)site * KTOP * DP;

    #pragma unroll
    for (int emb = 0; emb < 2; emb++){
        // h2[d][pair] = gelu(x @ W1 + b1); thread: k = tid&31, d = (tid>>5) + 8*it
        const int kk = tid & 31;
        #pragma unroll
        for (int it = 0; it < 16; it++){
            int d = (tid >> 5) + 8*it;
            float h = 0.f;
            if (kk < KTOP){
                float pre;
                if (emb == 0)
                    pre = S.b1a[d] + S.fe[0][kk]*S.w1a[d] + S.fe[1][kk]*S.w1a[DP+d]
                        + S.fe[2][kk]*S.w1a[2*DP+d] + S.fe[3][kk]*S.w1a[3*DP+d]
                        + S.fe[4][kk]*S.w1a[4*DP+d];
                else
                    pre = S.b1d[d] + S.fe[0][kk]*S.w1d[d] + S.fe[1][kk]*S.w1d[DP+d]
                        + S.fe[5][kk]*S.w1d[2*DP+d];
                h = gelu_t(pre);
            }
            ((float*)S.h2)[d*32 + kk] = h;
        }
        __syncthreads();

        // GEMM: warp tile = 8 pairs x 32 cols; h broadcast LDS.128, W2 direct LDG
        const float* __restrict__ Wg = emb ? Wd2 : Wa2;
        ull acc[8] = {0,0,0,0,0,0,0,0};
        #pragma unroll 4
        for (int d = 0; d < DP; d++){
            union { float4 v; ull u[2]; } A, B;
            const float4* hr = (const float4*)(S.h2 + d*16 + pbase);
            A.v = hr[0]; B.v = hr[1];
            ull wd = packdup(Wg[d*DP + c]);
            acc[0] = fma2(A.u[0], wd, acc[0]);
            acc[1] = fma2(A.u[1], wd, acc[1]);
            acc[2] = fma2(B.u[0], wd, acc[2]);
            acc[3] = fma2(B.u[1], wd, acc[3]);
            union { float4 v; ull u[2]; } C, D;
            C.v = hr[2]; D.v = hr[3];
            acc[4] = fma2(C.u[0], wd, acc[4]);
            acc[5] = fma2(C.u[1], wd, acc[5]);
            acc[6] = fma2(D.u[0], wd, acc[6]);
            acc[7] = fma2(D.u[1], wd, acc[7]);
        }
        float bv = (emb ? S.b2d : S.b2a)[c];
        float* __restrict__ og = emb ? out_dst : out_ang;
        #pragma unroll
        for (int p = 0; p < 8; p++){
            int r0 = 2*(pbase + p);
            float lo, hi; unpack2(acc[p], lo, hi);
            if (r0     < KTOP) og[base + (size_t)r0*DP + c]     = lo + bv;
            if (r0 + 1 < KTOP) og[base + (size_t)(r0+1)*DP + c] = hi + bv;
        }
        if (emb == 0) __syncthreads();   // everyone done reading h2 before refill
    }
}

__device__ __forceinline__ void relpos_role(
    unsigned char* smraw, int rblk,
    const int* __restrict__ ri,
    const float* __restrict__ W_rp, const float* __restrict__ b_rp,
    const float* __restrict__ W_tf, const float* __restrict__ b_tf,
    float* __restrict__ out_s, float* __restrict__ out_rp)
{
    SmemR& S = *reinterpret_cast<SmemR*>(smraw);
    const int tid = threadIdx.x;
    for (int e = tid; e < 65*DP; e += 256) S.T[e] = W_rp[e] + b_rp[e & 127];
    S.sv[tid] = W_tf[tid] + b_tf[tid];
    __syncthreads();

    if (tid < 64)
        ((float4*)out_s)[rblk*64 + tid] = ((const float4*)S.sv)[tid];

    const int lane = tid & 31;
    const int w    = tid >> 5;
    const int gw   = rblk*8 + w;          // 0..12287, 96 contiguous rows each
    const int r0   = gw * 96;
    const int bb   = r0 / (NRES*NRES);
    const int rem  = r0 - bb*(NRES*NRES);
    const int ii   = rem / NRES;
    const int jj0  = rem - ii*NRES;       // 96 | 768, chunk stays in one (bb,ii)
    const int rii  = ri[bb*NRES + ii];
    const int* __restrict__ rj = ri + bb*NRES + jj0;
    float4* __restrict__ dst = ((float4*)out_rp) + (size_t)r0*32 + lane;

    #pragma unroll 4
    for (int t = 0; t < 96; t++){
        int d = rii - rj[t];
        d = min(32, max(-32, d)) + 32;
        dst[(size_t)t*32] = ((const float4*)S.T)[d*32 + lane];
    }
}

__global__ __launch_bounds__(256, 4) void fused_kernel(
    const int* __restrict__ ri, const float* __restrict__ frames, const float* __restrict__ smask,
    const float* __restrict__ W_tf, const float* __restrict__ b_tf,
    const float* __restrict__ Wa1, const float* __restrict__ ba1,
    const float* __restrict__ Wa2, const float* __restrict__ ba2,
    const float* __restrict__ Wd1, const float* __restrict__ bd1,
    const float* __restrict__ Wd2, const float* __restrict__ bd2,
    const float* __restrict__ W_rp, const float* __restrict__ b_rp,
    float* __restrict__ out_s, float* __restrict__ out_ang,
    float* __restrict__ out_dst, float* __restrict__ out_rp)
{
    extern __shared__ unsigned char smraw[];
    const int bx = blockIdx.x;
    if ((bx & 1) == 0){
        embed_role(smraw, bx >> 1, ri, frames, smask,
                   Wa1, ba1, Wa2, ba2, Wd1, bd1, Wd2, bd2, out_ang, out_dst);
    } else {
        relpos_role(smraw, bx >> 1, ri, W_rp, b_rp, W_tf, b_tf, out_s, out_rp);
    }
}

extern "C" void kernel_launch(void* const* d_in, const int* in_sizes, int n_in,
                              void* d_out, int out_size)
{
    const int*   ri     = (const int*)  d_in[1];
    const float* frames = (const float*)d_in[2];
    const float* smaskp = (const float*)d_in[3];
    const float* W_tf   = (const float*)d_in[4];
    const float* b_tf   = (const float*)d_in[5];
    const float* Wa1    = (const float*)d_in[6];
    const float* ba1    = (const float*)d_in[7];
    const float* Wa2    = (const float*)d_in[8];
    const float* ba2    = (const float*)d_in[9];
    const float* Wd1    = (const float*)d_in[10];
    const float* bd1    = (const float*)d_in[11];
    const float* Wd2    = (const float*)d_in[12];
    const float* bd2    = (const float*)d_in[13];
    const float* W_rp   = (const float*)d_in[14];
    const float* b_rp   = (const float*)d_in[15];

    float* out     = (float*)d_out;
    float* out_s   = out;                                       // (2,768,256)
    float* out_ang = out_s   + (size_t)BATCH*NRES*256;          // (2,768,30,128)
    float* out_dst = out_ang + (size_t)BATCH*NRES*KTOP*DP;      // (2,768,30,128)
    float* out_rp  = out_dst + (size_t)BATCH*NRES*KTOP*DP;      // (2,768,768,128)

    int smem = (int)(sizeof(SmemE) > sizeof(SmemR) ? sizeof(SmemE) : sizeof(SmemR));
    cudaFuncSetAttribute(fused_kernel, cudaFuncAttributeMaxDynamicSharedMemorySize, smem);

    fused_kernel<<<NE + NRB, 256, smem>>>(
        ri, frames, smaskp, W_tf, b_tf,
        Wa1, ba1, Wa2, ba2, Wd1, bd1, Wd2, bd2, W_rp, b_rp,
        out_s, out_ang, out_dst, out_rp);
}

// round 4
// speedup vs baseline: 1.4539x; 1.0737x over previous
#include <cuda_runtime.h>
#include <math.h>

#define NRES 768
#define BATCH 2
#define KTOP 30
#define DP 128
#define INFV 1e10f
#define NE   (BATCH*NRES)          // 1536 embed sites (even blocks)
#define NRB  (BATCH*NRES)          // 1536 relpos blocks (odd blocks), one (b,i) each

typedef unsigned long long ull;

__device__ __forceinline__ ull fma2(ull a, ull b, ull c){
    ull d; asm("fma.rn.f32x2 %0, %1, %2, %3;" : "=l"(d) : "l"(a), "l"(b), "l"(c)); return d;
}
__device__ __forceinline__ ull packdup(float x){
    ull r; asm("mov.b64 %0, {%1, %2};" : "=l"(r) : "f"(x), "f"(x)); return r;
}
__device__ __forceinline__ void unpack2(ull v, float& lo, float& hi){
    asm("mov.b64 {%0, %1}, %2;" : "=f"(lo), "=f"(hi) : "l"(v));
}
__device__ __forceinline__ float gelu_t(float x){
    float x3 = x*x*x;
    return 0.5f*x*(1.0f + tanhf(0.7978845608028654f*(x + 0.044715f*x3)));
}
__device__ __forceinline__ unsigned okey(float v){
    unsigned u = __float_as_uint(v);
    return (u & 0x80000000u) ? ~u : (u | 0x80000000u);
}
__device__ __forceinline__ ull umin64(ull a, ull b){ return a < b ? a : b; }
__device__ __forceinline__ unsigned smem_u32(const void* p){
    unsigned a;
    asm("{ .reg .u64 t; cvta.to.shared.u64 t, %1; cvt.u32.u64 %0, t; }" : "=r"(a) : "l"(p));
    return a;
}

struct SmemE {
    ull   h2[DP*16];      // 16 KB: h2[d][pair] = (h[2p], h[2p+1]) packed f32x2
    ull   keys[NRES];     // 6 KB
    float dists[NRES];    // 3 KB
    float w1a[5*DP];
    float w1d[3*DP];
    float b1a[DP], b1d[DP], b2a[DP], b2d[DP];
    float fe[6][32];      // SoA feats
    float tiRi[12];
};
struct SmemR {
    float T[65*DP];       // 33.3 KB relpos table (TMA source)
    float sv[256];
};

__device__ __forceinline__ void embed_role(
    unsigned char* smraw, int site,
    const int* __restrict__ ri, const float* __restrict__ frames, const float* __restrict__ smask,
    const float* __restrict__ Wa1, const float* __restrict__ ba1,
    const float* __restrict__ Wa2, const float* __restrict__ ba2,
    const float* __restrict__ Wd1, const float* __restrict__ bd1,
    const float* __restrict__ Wd2, const float* __restrict__ bd2,
    float* __restrict__ out_ang, float* __restrict__ out_dst)
{
    SmemE& S = *reinterpret_cast<SmemE*>(smraw);
    const int tid = threadIdx.x;
    const int b  = site / NRES;
    const int i  = site - b*NRES;

    for (int e = tid; e < 5*DP; e += 256) S.w1a[e] = Wa1[e];
    for (int e = tid; e < 3*DP; e += 256) S.w1d[e] = Wd1[e];
    if (tid < DP){ S.b1a[tid]=ba1[tid]; S.b1d[tid]=bd1[tid]; S.b2a[tid]=ba2[tid]; S.b2d[tid]=bd2[tid]; }
    if (tid < 3) S.tiRi[tid] = frames[(size_t)(b*NRES+i)*16 + tid*4 + 3];
    if (tid >= 32 && tid < 41){
        int e = tid - 32;
        S.tiRi[3+e] = frames[(size_t)(b*NRES+i)*16 + (e/3)*4 + (e%3)];
    }
    __syncthreads();

    const float ti0 = S.tiRi[0], ti1 = S.tiRi[1], ti2 = S.tiRi[2];
    const int   rii = ri[b*NRES + i];
    const float mi  = smask[b*NRES + i];

    #pragma unroll
    for (int e = 0; e < 3; e++){
        int j = tid*3 + e;
        const float* fj = frames + (size_t)(b*NRES + j)*16;
        float dx = fj[3]-ti0, dy = fj[7]-ti1, dz = fj[11]-ti2;
        float d = sqrtf(dx*dx + dy*dy + dz*dz);
        S.dists[j] = d;
        bool conn = abs(rii - ri[b*NRES + j]) == 1;
        bool m = (mi != 0.f) && (smask[b*NRES + j] != 0.f);
        float v = conn ? -INFV : (!m ? INFV : ((j == i) ? INFV : d));
        S.keys[j] = ((ull)okey(v) << 32) | (unsigned)j;
    }
    __syncthreads();

    // warp0: top-30 via per-lane cached min + winner-only rescan
    if (tid < 32){
        const int lane = tid;
        ull mymin = ~0ull;
        #pragma unroll
        for (int e = 0; e < 24; e++) mymin = umin64(mymin, S.keys[e*32 + lane]);
        int mysel = -1;
        for (int it = 0; it < KTOP; it++){
            ull m = mymin;
            #pragma unroll
            for (int off = 16; off; off >>= 1)
                m = umin64(m, __shfl_xor_sync(0xffffffffu, m, off));
            if (it == lane) mysel = (int)(m & 0xffffffffu);
            if (m == mymin){
                S.keys[(int)(m & 0xffffffffu)] = ~0ull;
                ull t = ~0ull;
                #pragma unroll
                for (int e = 0; e < 24; e++) t = umin64(t, S.keys[e*32 + lane]);
                mymin = t;
            }
        }
        __syncwarp();
        if (lane < KTOP){
            int sel = mysel;
            const float* fj = frames + (size_t)(b*NRES + sel)*16;
            float dx = fj[3]-ti0, dy = fj[7]-ti1, dz = fj[11]-ti2;
            float d = S.dists[sel];
            float inv = (d > 0.f) ? (1.0f/d) : 0.f;
            float tr0 = S.tiRi[3+0]*dx + S.tiRi[3+3]*dy + S.tiRi[3+6]*dz;
            float tr1 = S.tiRi[3+1]*dx + S.tiRi[3+4]*dy + S.tiRi[3+7]*dz;
            float tr2 = S.tiRi[3+2]*dx + S.tiRi[3+5]*dy + S.tiRi[3+8]*dz;
            S.fe[0][lane] = (sel == i) ? 1.f : 0.f;
            S.fe[1][lane] = (abs(rii - ri[b*NRES + sel]) == 1) ? 1.f : 0.f;
            S.fe[2][lane] = tr0*inv;
            S.fe[3][lane] = tr1*inv;
            S.fe[4][lane] = tr2*inv;
            S.fe[5][lane] = d;
        } else {
            #pragma unroll
            for (int f = 0; f < 6; f++) S.fe[f][lane] = 0.f;
        }
    }
    __syncthreads();

    const int lane  = tid & 31;
    const int wq    = (tid >> 5) & 3;
    const int g     = tid >> 7;
    const int c     = wq*32 + lane;
    const int pbase = g*8;
    const size_t base = (size_t)site * KTOP * DP;

    #pragma unroll
    for (int emb = 0; emb < 2; emb++){
        const int kk = tid & 31;
        #pragma unroll
        for (int it = 0; it < 16; it++){
            int d = (tid >> 5) + 8*it;
            float h = 0.f;
            if (kk < KTOP){
                float pre;
                if (emb == 0)
                    pre = S.b1a[d] + S.fe[0][kk]*S.w1a[d] + S.fe[1][kk]*S.w1a[DP+d]
                        + S.fe[2][kk]*S.w1a[2*DP+d] + S.fe[3][kk]*S.w1a[3*DP+d]
                        + S.fe[4][kk]*S.w1a[4*DP+d];
                else
                    pre = S.b1d[d] + S.fe[0][kk]*S.w1d[d] + S.fe[1][kk]*S.w1d[DP+d]
                        + S.fe[5][kk]*S.w1d[2*DP+d];
                h = gelu_t(pre);
            }
            ((float*)S.h2)[d*32 + kk] = h;
        }
        __syncthreads();

        const float* __restrict__ Wg = emb ? Wd2 : Wa2;
        ull acc[8] = {0,0,0,0,0,0,0,0};
        #pragma unroll 4
        for (int d = 0; d < DP; d++){
            union { float4 v; ull u[2]; } A, B;
            const float4* hr = (const float4*)(S.h2 + d*16 + pbase);
            A.v = hr[0]; B.v = hr[1];
            ull wd = packdup(Wg[d*DP + c]);
            acc[0] = fma2(A.u[0], wd, acc[0]);
            acc[1] = fma2(A.u[1], wd, acc[1]);
            acc[2] = fma2(B.u[0], wd, acc[2]);
            acc[3] = fma2(B.u[1], wd, acc[3]);
            union { float4 v; ull u[2]; } C, D;
            C.v = hr[2]; D.v = hr[3];
            acc[4] = fma2(C.u[0], wd, acc[4]);
            acc[5] = fma2(C.u[1], wd, acc[5]);
            acc[6] = fma2(D.u[0], wd, acc[6]);
            acc[7] = fma2(D.u[1], wd, acc[7]);
        }
        float bv = (emb ? S.b2d : S.b2a)[c];
        float* __restrict__ og = emb ? out_dst : out_ang;
        #pragma unroll
        for (int p = 0; p < 8; p++){
            int r0 = 2*(pbase + p);
            float lo, hi; unpack2(acc[p], lo, hi);
            if (r0     < KTOP) og[base + (size_t)r0*DP + c]     = lo + bv;
            if (r0 + 1 < KTOP) og[base + (size_t)(r0+1)*DP + c] = hi + bv;
        }
        if (emb == 0) __syncthreads();
    }
}

// relpos: block = one (bb, ii); 768 rows written by TMA bulk copies from smem table
__device__ __forceinline__ void relpos_role(
    unsigned char* smraw, int rblk,
    const int* __restrict__ ri,
    const float* __restrict__ W_rp, const float* __restrict__ b_rp,
    const float* __restrict__ W_tf, const float* __restrict__ b_tf,
    float* __restrict__ out_s, float* __restrict__ out_rp)
{
    SmemR& S = *reinterpret_cast<SmemR*>(smraw);
    const int tid = threadIdx.x;
    for (int e = tid; e < 65*DP; e += 256) S.T[e] = W_rp[e] + b_rp[e & 127];
    S.sv[tid] = W_tf[tid] + b_tf[tid];
    asm volatile("fence.proxy.async.shared::cta;" ::: "memory");
    __syncthreads();

    if (tid < 64)
        ((float4*)out_s)[rblk*64 + tid] = ((const float4*)S.sv)[tid];

    const int bb  = rblk / NRES;
    const int ii  = rblk - bb*NRES;
    const int rii = ri[bb*NRES + ii];
    const int* __restrict__ rj = ri + bb*NRES;
    float* __restrict__ dst_base = out_rp + (size_t)rblk * NRES * DP;
    const unsigned tsm = smem_u32(S.T);

    #pragma unroll
    for (int t = 0; t < 3; t++){
        int jj = tid + t*256;
        int d = min(32, max(-32, rii - rj[jj])) + 32;
        unsigned src = tsm + (unsigned)d * 512u;
        asm volatile(
            "cp.async.bulk.global.shared::cta.bulk_group [%0], [%1], %2;"
            :: "l"(dst_base + (size_t)jj*DP), "r"(src), "r"(512u) : "memory");
    }
    asm volatile("cp.async.bulk.commit_group;" ::: "memory");
    asm volatile("cp.async.bulk.wait_group 0;" ::: "memory");
    __syncthreads();
}

__global__ __launch_bounds__(256, 4) void fused_kernel(
    const int* __restrict__ ri, const float* __restrict__ frames, const float* __restrict__ smask,
    const float* __restrict__ W_tf, const float* __restrict__ b_tf,
    const float* __restrict__ Wa1, const float* __restrict__ ba1,
    const float* __restrict__ Wa2, const float* __restrict__ ba2,
    const float* __restrict__ Wd1, const float* __restrict__ bd1,
    const float* __restrict__ Wd2, const float* __restrict__ bd2,
    const float* __restrict__ W_rp, const float* __restrict__ b_rp,
    float* __restrict__ out_s, float* __restrict__ out_ang,
    float* __restrict__ out_dst, float* __restrict__ out_rp)
{
    extern __shared__ unsigned char smraw[];
    const int bx = blockIdx.x;
    if ((bx & 1) == 0){
        embed_role(smraw, bx >> 1, ri, frames, smask,
                   Wa1, ba1, Wa2, ba2, Wd1, bd1, Wd2, bd2, out_ang, out_dst);
    } else {
        relpos_role(smraw, bx >> 1, ri, W_rp, b_rp, W_tf, b_tf, out_s, out_rp);
    }
}

extern "C" void kernel_launch(void* const* d_in, const int* in_sizes, int n_in,
                              void* d_out, int out_size)
{
    const int*   ri     = (const int*)  d_in[1];
    const float* frames = (const float*)d_in[2];
    const float* smaskp = (const float*)d_in[3];
    const float* W_tf   = (const float*)d_in[4];
    const float* b_tf   = (const float*)d_in[5];
    const float* Wa1    = (const float*)d_in[6];
    const float* ba1    = (const float*)d_in[7];
    const float* Wa2    = (const float*)d_in[8];
    const float* ba2    = (const float*)d_in[9];
    const float* Wd1    = (const float*)d_in[10];
    const float* bd1    = (const float*)d_in[11];
    const float* Wd2    = (const float*)d_in[12];
    const float* bd2    = (const float*)d_in[13];
    const float* W_rp   = (const float*)d_in[14];
    const float* b_rp   = (const float*)d_in[15];

    float* out     = (float*)d_out;
    float* out_s   = out;                                       // (2,768,256)
    float* out_ang = out_s   + (size_t)BATCH*NRES*256;          // (2,768,30,128)
    float* out_dst = out_ang + (size_t)BATCH*NRES*KTOP*DP;      // (2,768,30,128)
    float* out_rp  = out_dst + (size_t)BATCH*NRES*KTOP*DP;      // (2,768,768,128)

    int smem = (int)(sizeof(SmemE) > sizeof(SmemR) ? sizeof(SmemE) : sizeof(SmemR));
    cudaFuncSetAttribute(fused_kernel, cudaFuncAttributeMaxDynamicSharedMemorySize, smem);

    fused_kernel<<<NE + NRB, 256, smem>>>(
        ri, frames, smaskp, W_tf, b_tf,
        Wa1, ba1, Wa2, ba2, Wd1, bd1, Wd2, bd2, W_rp, b_rp,
        out_s, out_ang, out_dst, out_rp);
}